// round 7
// baseline (speedup 1.0000x reference)
#include <cuda_runtime.h>
#include <cuda_bf16.h>
#include <cstdint>

#define N       8192
#define D       128
#define BM      128
#define BN      128
#define NB      64          // number of 128-row blocks
#define P       16
#define MARGINF 1.0f
#define EPSF    1e-12f
#define FINF    __int_as_float(0x7f800000)
#define INFBITS 0x7f800000

// smem layout (dynamic, 192KB): A hi | A lo | B buf0 (hi|lo) | B buf1 (hi|lo)
#define SMA_HI  0u
#define SMA_LO  32768u
#define SMB0    65536u
#define SMB_SZ  65536u      // hi 32KB + lo 32KB per buffer

// Scratch (no allocation allowed -> device globals)
__device__ float g_sq[N];
__device__ int   g_maxp[N];     // float bits, mined via order-independent atomics
__device__ int   g_minn[N];
__device__ float g_cn[P * D];
__device__ float g_partials[N / 64];
__device__ __nv_bfloat16 g_xhi[N * D];
__device__ __nv_bfloat16 g_xlo[N * D];

// ---------------------------------------------------------------------------
static __device__ __forceinline__ uint32_t smem_u32(const void* p) {
    uint32_t a;
    asm("{ .reg .u64 t; cvta.to.shared.u64 t, %1; cvt.u32.u64 %0, t; }" : "=r"(a) : "l"(p));
    return a;
}
static __device__ __forceinline__ void ldsm4(uint32_t* r, uint32_t addr) {
    asm volatile("ldmatrix.sync.aligned.m8n8.x4.shared.b16 {%0,%1,%2,%3}, [%4];"
                 : "=r"(r[0]), "=r"(r[1]), "=r"(r[2]), "=r"(r[3]) : "r"(addr));
}
static __device__ __forceinline__ void mma16816(float* c, const uint32_t* a,
                                                const uint32_t* b) {
    asm volatile("mma.sync.aligned.m16n8k16.row.col.f32.bf16.bf16.f32 "
                 "{%0,%1,%2,%3}, {%4,%5,%6,%7}, {%8,%9}, {%0,%1,%2,%3};"
                 : "+f"(c[0]), "+f"(c[1]), "+f"(c[2]), "+f"(c[3])
                 : "r"(a[0]), "r"(a[1]), "r"(a[2]), "r"(a[3]), "r"(b[0]), "r"(b[1]));
}
static __device__ __forceinline__ void cpa16(uint32_t dst, const void* src) {
    asm volatile("cp.async.cg.shared.global [%0], [%1], 16;" :: "r"(dst), "l"(src) : "memory");
}
#define CPA_COMMIT() asm volatile("cp.async.commit_group;" ::: "memory")
#define CPA_WAIT(n)  asm volatile("cp.async.wait_group %0;" :: "n"(n) : "memory")

// 128x128 bf16 tile -> smem, row-major 256B rows, 16B-chunk xor swizzle.
static __device__ __forceinline__ void cpa_tile(uint32_t dst_s,
                                                const __nv_bfloat16* src,
                                                int row0, int tid) {
    const char* base = (const char*)(src + (size_t)row0 * D);
    #pragma unroll
    for (int i = 0; i < 8; i++) {
        int idx = tid + i * 256;
        int r = idx >> 4, c = idx & 15;
        uint32_t off = (uint32_t)r * 256 + (uint32_t)((c ^ (r & 7)) << 4);
        cpa16(dst_s + off, base + (size_t)r * 256 + c * 16);
    }
}

// ---------------------------------------------------------------------------
// Fused prep: one warp per row -> bf16 hi/lo split, squared norm, mined init.
__global__ void k_split(const float* __restrict__ X) {
    int w = (blockIdx.x * blockDim.x + threadIdx.x) >> 5;
    int lane = threadIdx.x & 31;
    if (w >= N) return;
    float4 v = ((const float4*)X)[(size_t)w * (D / 4) + lane];
    __nv_bfloat16 h0 = __float2bfloat16(v.x), h1 = __float2bfloat16(v.y);
    __nv_bfloat16 h2 = __float2bfloat16(v.z), h3 = __float2bfloat16(v.w);
    __nv_bfloat16 l0 = __float2bfloat16(v.x - __bfloat162float(h0));
    __nv_bfloat16 l1 = __float2bfloat16(v.y - __bfloat162float(h1));
    __nv_bfloat16 l2 = __float2bfloat16(v.z - __bfloat162float(h2));
    __nv_bfloat16 l3 = __float2bfloat16(v.w - __bfloat162float(h3));
    size_t o = (size_t)w * (D / 2) + lane * 2;
    ((__nv_bfloat162*)g_xhi)[o]     = __nv_bfloat162(h0, h1);
    ((__nv_bfloat162*)g_xhi)[o + 1] = __nv_bfloat162(h2, h3);
    ((__nv_bfloat162*)g_xlo)[o]     = __nv_bfloat162(l0, l1);
    ((__nv_bfloat162*)g_xlo)[o + 1] = __nv_bfloat162(l2, l3);
    float s = v.x * v.x + v.y * v.y + v.z * v.z + v.w * v.w;
    #pragma unroll
    for (int off = 16; off; off >>= 1) s += __shfl_xor_sync(0xffffffffu, s, off);
    if (lane == 0) { g_sq[w] = s; g_maxp[w] = 0; g_minn[w] = INFBITS; }
}

__global__ void k_prep(const float* __restrict__ C) {
    int w = threadIdx.x >> 5;
    int lane = threadIdx.x & 31;
    if (w >= P) return;
    const float4* c4 = (const float4*)(C + (size_t)w * D);
    float4 v = c4[lane];
    float s = v.x * v.x + v.y * v.y + v.z * v.z + v.w * v.w;
    #pragma unroll
    for (int o = 16; o; o >>= 1) s += __shfl_xor_sync(0xffffffffu, s, o);
    float inv = 1.0f / sqrtf(s);
    float* dst = g_cn + (size_t)w * D + lane * 4;
    dst[0] = v.x * inv; dst[1] = v.y * inv; dst[2] = v.z * inv; dst[3] = v.w * inv;
}

// ---------------------------------------------------------------------------
// Symmetric mining: block (I, s) computes tiles (I, (I+k)%64), k in its chunk.
// One __syncthreads per tile; col stats go straight to global atomics.
__global__ void __launch_bounds__(256, 1)
k_main(const float* __restrict__ X, const int* __restrict__ T) {
    extern __shared__ __align__(1024) char smem[];
    __shared__ int   tCol[2][BN];
    __shared__ float sqCol[2][BN];
    __shared__ float redmax[2][BM];
    __shared__ float redmin[2][BM];
    __shared__ int   s_J[2];

    const int tid  = threadIdx.x;
    const int wid  = tid >> 5;
    const int lane = tid & 31;
    const int mw   = wid & 3;
    const int nh   = wid >> 2;
    const int wm0  = mw * 32;
    const int wn0  = nh * 64;
    const int I    = blockIdx.x;
    const int sch  = blockIdx.y;       // 0: k=0..16, 1: k=17..32
    const int kbeg = sch ? 17 : 0;
    const int kcnt = sch ? 16 : 17;
    const int row0 = I * BM;
    const uint32_t sb = smem_u32(smem);

    float sqr[2][2]; int trow[2][2];
    #pragma unroll
    for (int i = 0; i < 2; i++)
        #pragma unroll
        for (int h = 0; h < 2; h++) {
            int gr = row0 + wm0 + i * 16 + h * 8 + (lane >> 2);
            sqr[i][h] = g_sq[gr];
            trow[i][h] = T[gr];
        }

    uint32_t a_rowoff[2], b_coloff[4];
    const uint32_t a_chk = (uint32_t)(lane >> 4);
    const uint32_t b_chk = (uint32_t)((lane >> 3) & 1);
    #pragma unroll
    for (int i = 0; i < 2; i++) {
        uint32_t r = wm0 + i * 16 + (lane & 7) + ((lane >> 3) & 1) * 8;
        a_rowoff[i] = (r * 256) | ((r & 7) << 28);
    }
    #pragma unroll
    for (int jj = 0; jj < 4; jj++) {
        uint32_t c = wn0 + jj * 16 + (lane & 7) + (lane >> 4) * 8;
        b_coloff[jj] = (c * 256) | ((c & 7) << 28);
    }

    // Prologue
    cpa_tile(sb + SMA_HI, g_xhi, row0, tid);
    cpa_tile(sb + SMA_LO, g_xlo, row0, tid);
    {
        int J0 = (I + kbeg) & (NB - 1);
        cpa_tile(sb + SMB0,          g_xhi, J0 * BN, tid);
        cpa_tile(sb + SMB0 + 32768u, g_xlo, J0 * BN, tid);
        if (tid < BN) { tCol[0][tid] = T[J0 * BN + tid]; sqCol[0][tid] = g_sq[J0 * BN + tid]; }
        if (tid == 0) s_J[0] = J0;
    }
    CPA_COMMIT();

    float mp[2][2], mn[2][2];
    #pragma unroll
    for (int i = 0; i < 2; i++)
        #pragma unroll
        for (int h = 0; h < 2; h++) { mp[i][h] = -1.0f; mn[i][h] = FINF; }

    for (int t = 0; t < kcnt; t++) {
        const uint32_t buf = (uint32_t)(t & 1);
        CPA_WAIT(0);
        __syncthreads();        // tile t resident; everyone done with buf^1 (tile t-1)

        if (t + 1 < kcnt) {
            int J1 = (I + kbeg + t + 1) & (NB - 1);
            cpa_tile(sb + SMB0 + (buf ^ 1) * SMB_SZ,          g_xhi, J1 * BN, tid);
            cpa_tile(sb + SMB0 + (buf ^ 1) * SMB_SZ + 32768u, g_xlo, J1 * BN, tid);
            CPA_COMMIT();
            if (tid < BN) {
                tCol[buf ^ 1][tid] = T[J1 * BN + tid];
                sqCol[buf ^ 1][tid] = g_sq[J1 * BN + tid];
            }
            if (tid == 0) s_J[buf ^ 1] = J1;
        }

        float acc[2][8][4];
        #pragma unroll
        for (int i = 0; i < 2; i++)
            #pragma unroll
            for (int j = 0; j < 8; j++)
                #pragma unroll
                for (int e = 0; e < 4; e++) acc[i][j][e] = 0.0f;

        const uint32_t ab_hi = sb + SMA_HI;
        const uint32_t ab_lo = sb + SMA_LO;
        const uint32_t bb_hi = sb + SMB0 + buf * SMB_SZ;
        const uint32_t bb_lo = bb_hi + 32768u;

        #pragma unroll
        for (int ks = 0; ks < 8; ks++) {
            uint32_t a_hi[2][4], a_lo[2][4], b_hi[4][4], b_lo[4][4];
            const uint32_t achunk = (uint32_t)(2 * ks) + a_chk;
            const uint32_t bchunk = (uint32_t)(2 * ks) + b_chk;
            #pragma unroll
            for (int i = 0; i < 2; i++) {
                uint32_t ro = a_rowoff[i];
                uint32_t off = (ro & 0x0FFFFFFFu) + ((achunk ^ (ro >> 28)) << 4);
                ldsm4(a_hi[i], ab_hi + off);
                ldsm4(a_lo[i], ab_lo + off);
            }
            #pragma unroll
            for (int jj = 0; jj < 4; jj++) {
                uint32_t co = b_coloff[jj];
                uint32_t off = (co & 0x0FFFFFFFu) + ((bchunk ^ (co >> 28)) << 4);
                ldsm4(b_hi[jj], bb_hi + off);
                ldsm4(b_lo[jj], bb_lo + off);
            }
            // Three full sweeps -> same-acc writes spaced 16 MMAs apart.
            #pragma unroll
            for (int i = 0; i < 2; i++)
                #pragma unroll
                for (int jj = 0; jj < 4; jj++) {
                    mma16816(acc[i][2 * jj],     a_hi[i], &b_hi[jj][0]);
                    mma16816(acc[i][2 * jj + 1], a_hi[i], &b_hi[jj][2]);
                }
            #pragma unroll
            for (int i = 0; i < 2; i++)
                #pragma unroll
                for (int jj = 0; jj < 4; jj++) {
                    mma16816(acc[i][2 * jj],     a_hi[i], &b_lo[jj][0]);
                    mma16816(acc[i][2 * jj + 1], a_hi[i], &b_lo[jj][2]);
                }
            #pragma unroll
            for (int i = 0; i < 2; i++)
                #pragma unroll
                for (int jj = 0; jj < 4; jj++) {
                    mma16816(acc[i][2 * jj],     a_lo[i], &b_hi[jj][0]);
                    mma16816(acc[i][2 * jj + 1], a_lo[i], &b_hi[jj][2]);
                }
        }

        // Fused mining: row stats (registers) + col stats (per tile).
        float cmax[8][2], cmin[8][2];
        #pragma unroll
        for (int j = 0; j < 8; j++) { cmax[j][0] = cmax[j][1] = -1.0f;
                                      cmin[j][0] = cmin[j][1] = FINF; }
        #pragma unroll
        for (int j = 0; j < 8; j++) {
            int cb = wn0 + j * 8 + (lane & 3) * 2;
            int tc0 = tCol[buf][cb], tc1 = tCol[buf][cb + 1];
            float sc0 = sqCol[buf][cb], sc1 = sqCol[buf][cb + 1];
            #pragma unroll
            for (int i = 0; i < 2; i++)
                #pragma unroll
                for (int h = 0; h < 2; h++) {
                    float d0 = fmaxf(fmaf(-2.0f, acc[i][j][2 * h],     sqr[i][h] + sc0), 0.0f);
                    float d1 = fmaxf(fmaf(-2.0f, acc[i][j][2 * h + 1], sqr[i][h] + sc1), 0.0f);
                    if (trow[i][h] == tc0) { mp[i][h] = fmaxf(mp[i][h], d0);
                                             cmax[j][0] = fmaxf(cmax[j][0], d0); }
                    else                   { mn[i][h] = fminf(mn[i][h], d0);
                                             cmin[j][0] = fminf(cmin[j][0], d0); }
                    if (trow[i][h] == tc1) { mp[i][h] = fmaxf(mp[i][h], d1);
                                             cmax[j][1] = fmaxf(cmax[j][1], d1); }
                    else                   { mn[i][h] = fminf(mn[i][h], d1);
                                             cmin[j][1] = fminf(cmin[j][1], d1); }
                }
        }
        // Butterfly over the 8 row-lane-groups, then direct global atomics
        // (no-return REDG; order-independent for min/max -> deterministic).
        #pragma unroll
        for (int j = 0; j < 8; j++)
            #pragma unroll
            for (int e = 0; e < 2; e++) {
                #pragma unroll
                for (int o = 4; o <= 16; o <<= 1) {
                    cmax[j][e] = fmaxf(cmax[j][e], __shfl_xor_sync(0xffffffffu, cmax[j][e], o));
                    cmin[j][e] = fminf(cmin[j][e], __shfl_xor_sync(0xffffffffu, cmin[j][e], o));
                }
            }
        if (lane < 4) {
            int colbase = s_J[buf] * BN + wn0;
            #pragma unroll
            for (int j = 0; j < 8; j++)
                #pragma unroll
                for (int e = 0; e < 2; e++) {
                    int gcol = colbase + j * 8 + lane * 2 + e;
                    atomicMax(&g_maxp[gcol], __float_as_int(cmax[j][e]));
                    atomicMin(&g_minn[gcol], __float_as_int(cmin[j][e]));
                }
        }
    }

    // Row stats: reduce over 4 lanes/row, then 2 N-halves, then atomics.
    #pragma unroll
    for (int i = 0; i < 2; i++)
        #pragma unroll
        for (int h = 0; h < 2; h++) {
            #pragma unroll
            for (int o = 1; o <= 2; o <<= 1) {
                mp[i][h] = fmaxf(mp[i][h], __shfl_xor_sync(0xffffffffu, mp[i][h], o));
                mn[i][h] = fminf(mn[i][h], __shfl_xor_sync(0xffffffffu, mn[i][h], o));
            }
            if ((lane & 3) == 0) {
                int r = wm0 + i * 16 + h * 8 + (lane >> 2);
                redmax[nh][r] = mp[i][h];
                redmin[nh][r] = mn[i][h];
            }
        }
    __syncthreads();
    if (tid < BM) {
        float rmax = fmaxf(redmax[0][tid], redmax[1][tid]);
        float rmin = fminf(redmin[0][tid], redmin[1][tid]);
        atomicMax(&g_maxp[row0 + tid], __float_as_int(rmax));
        atomicMin(&g_minn[row0 + tid], __float_as_int(rmin));
    }
}

// ---------------------------------------------------------------------------
// Finalize: 64 rows/block (grid 128, one wave); thread (q,r,c) layout:
// c = tid&15 (center), rslot = tid>>4 (16 slots), each slot does 4 rows.
__global__ void k_finalize(const float* __restrict__ X) {
    __shared__ float xs[64 * D];
    __shared__ float cnt[D * 16];
    __shared__ float terms[64];
    const int b = blockIdx.x, tid = threadIdx.x;
    const int row0 = b * 64;

    for (int i = tid; i < 64 * D; i += 256) xs[i] = X[(size_t)row0 * D + i];
    for (int i = tid; i < P * D; i += 256) {
        int k = i >> 4, c = i & 15;
        cnt[k * 16 + c] = g_cn[c * D + k];
    }
    __syncthreads();

    const int rslot = tid >> 4, c = tid & 15;
    #pragma unroll
    for (int q = 0; q < 4; q++) {
        int r = rslot * 4 + q;
        float d2 = 0.0f;
        #pragma unroll 8
        for (int k = 0; k < D; k++) {
            float diff = xs[r * D + k] - cnt[k * 16 + c];
            d2 = fmaf(diff, diff, d2);
        }
        float dc = fmaxf(sqrtf(d2), EPSF);
        #pragma unroll
        for (int o = 8; o; o >>= 1) dc = fminf(dc, __shfl_xor_sync(0xffffffffu, dc, o));
        if (c == 0) {
            int row = row0 + r;
            float mpv = __int_as_float(g_maxp[row]);
            float mnv = __int_as_float(g_minn[row]);
            float dap = sqrtf(fmaxf(mpv, EPSF));
            float dan = isinf(mnv) ? (dap + MARGINF) : sqrtf(fmaxf(mnv, EPSF));
            dan = fminf(dan, dc);
            terms[r] = fmaxf(dap - dan + MARGINF, 0.0f);
        }
    }
    __syncthreads();
    if (tid == 0) {
        float s = 0.0f;
        #pragma unroll
        for (int i = 0; i < 64; i++) s += terms[i];
        g_partials[b] = s;
    }
}

__global__ void k_sum(float* __restrict__ out) {
    __shared__ float sh[128];
    int t = threadIdx.x;
    sh[t] = g_partials[t];
    __syncthreads();
    for (int s = 64; s; s >>= 1) {
        if (t < s) sh[t] += sh[t + s];
        __syncthreads();
    }
    if (t == 0) out[0] = sh[0] / (float)N;
}

// ---------------------------------------------------------------------------
extern "C" void kernel_launch(void* const* d_in, const int* in_sizes, int n_in,
                              void* d_out, int out_size) {
    const float* X = (const float*)d_in[0];
    const int*   T = (const int*)d_in[1];
    const float* C = (const float*)d_in[2];
    float* out = (float*)d_out;

    size_t smem = 196608;   // A hi/lo 64KB + B double buffer 128KB
    cudaFuncSetAttribute(k_main, cudaFuncAttributeMaxDynamicSharedMemorySize, (int)smem);

    k_split<<<N / 8, 256>>>(X);
    k_prep<<<1, P * 32>>>(C);
    k_main<<<dim3(NB, 2), 256, smem>>>(X, T);
    k_finalize<<<N / 64, 256>>>(X);
    k_sum<<<1, 128>>>(out);
}

// round 8
// speedup vs baseline: 1.0203x; 1.0203x over previous
#include <cuda_runtime.h>
#include <cuda_bf16.h>
#include <cstdint>

#define N       8192
#define D       128
#define BM      128
#define BN      128
#define NB      64          // number of 128-row blocks
#define P       16
#define MARGINF 1.0f
#define EPSF    1e-12f
#define FINF    __int_as_float(0x7f800000)
#define INFBITS 0x7f800000

// smem layout (dynamic, 192KB): A hi | A lo | B buf0 (hi|lo) | B buf1 (hi|lo)
#define SMA_HI  0u
#define SMA_LO  32768u
#define SMB0    65536u
#define SMB_SZ  65536u      // hi 32KB + lo 32KB per buffer

// Scratch (no allocation allowed -> device globals)
__device__ float g_sq[N];
__device__ int   g_maxp[N];     // float bits, mined via order-independent atomics
__device__ int   g_minn[N];
__device__ float g_cn[P * D];
__device__ float g_partials[N / 16];
__device__ __nv_bfloat16 g_xhi[N * D];
__device__ __nv_bfloat16 g_xlo[N * D];

// ---------------------------------------------------------------------------
static __device__ __forceinline__ uint32_t smem_u32(const void* p) {
    uint32_t a;
    asm("{ .reg .u64 t; cvta.to.shared.u64 t, %1; cvt.u32.u64 %0, t; }" : "=r"(a) : "l"(p));
    return a;
}
static __device__ __forceinline__ void ldsm4(uint32_t* r, uint32_t addr) {
    asm volatile("ldmatrix.sync.aligned.m8n8.x4.shared.b16 {%0,%1,%2,%3}, [%4];"
                 : "=r"(r[0]), "=r"(r[1]), "=r"(r[2]), "=r"(r[3]) : "r"(addr));
}
static __device__ __forceinline__ void mma16816(float* c, const uint32_t* a,
                                                const uint32_t* b) {
    asm volatile("mma.sync.aligned.m16n8k16.row.col.f32.bf16.bf16.f32 "
                 "{%0,%1,%2,%3}, {%4,%5,%6,%7}, {%8,%9}, {%0,%1,%2,%3};"
                 : "+f"(c[0]), "+f"(c[1]), "+f"(c[2]), "+f"(c[3])
                 : "r"(a[0]), "r"(a[1]), "r"(a[2]), "r"(a[3]), "r"(b[0]), "r"(b[1]));
}
static __device__ __forceinline__ void cpa16(uint32_t dst, const void* src) {
    asm volatile("cp.async.cg.shared.global [%0], [%1], 16;" :: "r"(dst), "l"(src) : "memory");
}
#define CPA_COMMIT() asm volatile("cp.async.commit_group;" ::: "memory")
#define CPA_WAIT(n)  asm volatile("cp.async.wait_group %0;" :: "n"(n) : "memory")

// 128x128 bf16 tile -> smem, row-major 256B rows, 16B-chunk xor swizzle.
// 512 threads: 4 chunks each.
static __device__ __forceinline__ void cpa_tile(uint32_t dst_s,
                                                const __nv_bfloat16* src,
                                                int row0, int tid) {
    const char* base = (const char*)(src + (size_t)row0 * D);
    #pragma unroll
    for (int i = 0; i < 4; i++) {
        int idx = tid + i * 512;
        int r = idx >> 4, c = idx & 15;
        uint32_t off = (uint32_t)r * 256 + (uint32_t)((c ^ (r & 7)) << 4);
        cpa16(dst_s + off, base + (size_t)r * 256 + c * 16);
    }
}

// ---------------------------------------------------------------------------
// Fused prep: one warp per row -> bf16 hi/lo split, squared norm, mined init.
__global__ void k_split(const float* __restrict__ X) {
    int w = (blockIdx.x * blockDim.x + threadIdx.x) >> 5;
    int lane = threadIdx.x & 31;
    if (w >= N) return;
    float4 v = ((const float4*)X)[(size_t)w * (D / 4) + lane];
    __nv_bfloat16 h0 = __float2bfloat16(v.x), h1 = __float2bfloat16(v.y);
    __nv_bfloat16 h2 = __float2bfloat16(v.z), h3 = __float2bfloat16(v.w);
    __nv_bfloat16 l0 = __float2bfloat16(v.x - __bfloat162float(h0));
    __nv_bfloat16 l1 = __float2bfloat16(v.y - __bfloat162float(h1));
    __nv_bfloat16 l2 = __float2bfloat16(v.z - __bfloat162float(h2));
    __nv_bfloat16 l3 = __float2bfloat16(v.w - __bfloat162float(h3));
    size_t o = (size_t)w * (D / 2) + lane * 2;
    ((__nv_bfloat162*)g_xhi)[o]     = __nv_bfloat162(h0, h1);
    ((__nv_bfloat162*)g_xhi)[o + 1] = __nv_bfloat162(h2, h3);
    ((__nv_bfloat162*)g_xlo)[o]     = __nv_bfloat162(l0, l1);
    ((__nv_bfloat162*)g_xlo)[o + 1] = __nv_bfloat162(l2, l3);
    float s = v.x * v.x + v.y * v.y + v.z * v.z + v.w * v.w;
    #pragma unroll
    for (int off = 16; off; off >>= 1) s += __shfl_xor_sync(0xffffffffu, s, off);
    if (lane == 0) { g_sq[w] = s; g_maxp[w] = 0; g_minn[w] = INFBITS; }
}

__global__ void k_prep(const float* __restrict__ C) {
    int w = threadIdx.x >> 5;
    int lane = threadIdx.x & 31;
    if (w >= P) return;
    const float4* c4 = (const float4*)(C + (size_t)w * D);
    float4 v = c4[lane];
    float s = v.x * v.x + v.y * v.y + v.z * v.z + v.w * v.w;
    #pragma unroll
    for (int o = 16; o; o >>= 1) s += __shfl_xor_sync(0xffffffffu, s, o);
    float inv = 1.0f / sqrtf(s);
    float* dst = g_cn + (size_t)w * D + lane * 4;
    dst[0] = v.x * inv; dst[1] = v.y * inv; dst[2] = v.z * inv; dst[3] = v.w * inv;
}

// ---------------------------------------------------------------------------
// Symmetric mining: block (I, s) computes tiles (I, (I+k)%64), k in its chunk.
// 512 threads, 16 warps in a 4x4 grid: warp tile 32 rows x 32 cols.
__global__ void __launch_bounds__(512, 1)
k_main(const float* __restrict__ X, const int* __restrict__ T) {
    extern __shared__ __align__(1024) char smem[];
    __shared__ int   tCol[2][BN];
    __shared__ float sqCol[2][BN];
    __shared__ int   s_J[2];

    const int tid  = threadIdx.x;
    const int wid  = tid >> 5;
    const int lane = tid & 31;
    const int mw   = wid & 3;          // M-warp (32 rows)
    const int nq   = wid >> 2;         // N-quarter (32 cols)
    const int wm0  = mw * 32;
    const int wn0  = nq * 32;
    const int I    = blockIdx.x;
    const int sch  = blockIdx.y;       // 0: k=0..16, 1: k=17..32
    const int kbeg = sch ? 17 : 0;
    const int kcnt = sch ? 16 : 17;
    const int row0 = I * BM;
    const uint32_t sb = smem_u32(smem);

    float sqr[2][2]; int trow[2][2];
    #pragma unroll
    for (int i = 0; i < 2; i++)
        #pragma unroll
        for (int h = 0; h < 2; h++) {
            int gr = row0 + wm0 + i * 16 + h * 8 + (lane >> 2);
            sqr[i][h] = g_sq[gr];
            trow[i][h] = T[gr];
        }

    uint32_t a_rowoff[2], b_coloff[2];
    const uint32_t a_chk = (uint32_t)(lane >> 4);
    const uint32_t b_chk = (uint32_t)((lane >> 3) & 1);
    #pragma unroll
    for (int i = 0; i < 2; i++) {
        uint32_t r = wm0 + i * 16 + (lane & 7) + ((lane >> 3) & 1) * 8;
        a_rowoff[i] = (r * 256) | ((r & 7) << 28);
    }
    #pragma unroll
    for (int jj = 0; jj < 2; jj++) {
        uint32_t c = wn0 + jj * 16 + (lane & 7) + (lane >> 4) * 8;
        b_coloff[jj] = (c * 256) | ((c & 7) << 28);
    }

    // Prologue
    cpa_tile(sb + SMA_HI, g_xhi, row0, tid);
    cpa_tile(sb + SMA_LO, g_xlo, row0, tid);
    {
        int J0 = (I + kbeg) & (NB - 1);
        cpa_tile(sb + SMB0,          g_xhi, J0 * BN, tid);
        cpa_tile(sb + SMB0 + 32768u, g_xlo, J0 * BN, tid);
        if (tid < BN) { tCol[0][tid] = T[J0 * BN + tid]; sqCol[0][tid] = g_sq[J0 * BN + tid]; }
        if (tid == 0) s_J[0] = J0;
    }
    CPA_COMMIT();

    float mp[2][2], mn[2][2];
    #pragma unroll
    for (int i = 0; i < 2; i++)
        #pragma unroll
        for (int h = 0; h < 2; h++) { mp[i][h] = -1.0f; mn[i][h] = FINF; }

    for (int t = 0; t < kcnt; t++) {
        const uint32_t buf = (uint32_t)(t & 1);
        CPA_WAIT(0);
        __syncthreads();        // tile t resident; everyone done with buf^1

        if (t + 1 < kcnt) {
            int J1 = (I + kbeg + t + 1) & (NB - 1);
            cpa_tile(sb + SMB0 + (buf ^ 1) * SMB_SZ,          g_xhi, J1 * BN, tid);
            cpa_tile(sb + SMB0 + (buf ^ 1) * SMB_SZ + 32768u, g_xlo, J1 * BN, tid);
            CPA_COMMIT();
            if (tid < BN) {
                tCol[buf ^ 1][tid] = T[J1 * BN + tid];
                sqCol[buf ^ 1][tid] = g_sq[J1 * BN + tid];
            }
            if (tid == 0) s_J[buf ^ 1] = J1;
        }

        float acc[2][4][4];
        #pragma unroll
        for (int i = 0; i < 2; i++)
            #pragma unroll
            for (int j = 0; j < 4; j++)
                #pragma unroll
                for (int e = 0; e < 4; e++) acc[i][j][e] = 0.0f;

        const uint32_t ab_hi = sb + SMA_HI;
        const uint32_t ab_lo = sb + SMA_LO;
        const uint32_t bb_hi = sb + SMB0 + buf * SMB_SZ;
        const uint32_t bb_lo = bb_hi + 32768u;

        #pragma unroll
        for (int ks = 0; ks < 8; ks++) {
            uint32_t a_hi[2][4], a_lo[2][4], b_hi[2][4], b_lo[2][4];
            const uint32_t achunk = (uint32_t)(2 * ks) + a_chk;
            const uint32_t bchunk = (uint32_t)(2 * ks) + b_chk;
            #pragma unroll
            for (int i = 0; i < 2; i++) {
                uint32_t ro = a_rowoff[i];
                uint32_t off = (ro & 0x0FFFFFFFu) + ((achunk ^ (ro >> 28)) << 4);
                ldsm4(a_hi[i], ab_hi + off);
                ldsm4(a_lo[i], ab_lo + off);
            }
            #pragma unroll
            for (int jj = 0; jj < 2; jj++) {
                uint32_t co = b_coloff[jj];
                uint32_t off = (co & 0x0FFFFFFFu) + ((bchunk ^ (co >> 28)) << 4);
                ldsm4(b_hi[jj], bb_hi + off);
                ldsm4(b_lo[jj], bb_lo + off);
            }
            // Three sweeps: hi*hi, hi*lo, lo*hi — same-acc writes spaced 8 apart.
            #pragma unroll
            for (int i = 0; i < 2; i++)
                #pragma unroll
                for (int jj = 0; jj < 2; jj++) {
                    mma16816(acc[i][2 * jj],     a_hi[i], &b_hi[jj][0]);
                    mma16816(acc[i][2 * jj + 1], a_hi[i], &b_hi[jj][2]);
                }
            #pragma unroll
            for (int i = 0; i < 2; i++)
                #pragma unroll
                for (int jj = 0; jj < 2; jj++) {
                    mma16816(acc[i][2 * jj],     a_hi[i], &b_lo[jj][0]);
                    mma16816(acc[i][2 * jj + 1], a_hi[i], &b_lo[jj][2]);
                }
            #pragma unroll
            for (int i = 0; i < 2; i++)
                #pragma unroll
                for (int jj = 0; jj < 2; jj++) {
                    mma16816(acc[i][2 * jj],     a_lo[i], &b_hi[jj][0]);
                    mma16816(acc[i][2 * jj + 1], a_lo[i], &b_hi[jj][2]);
                }
        }

        // Fused mining: row stats (registers) + col stats (per tile).
        float cmax[4][2], cmin[4][2];
        #pragma unroll
        for (int j = 0; j < 4; j++) { cmax[j][0] = cmax[j][1] = -1.0f;
                                      cmin[j][0] = cmin[j][1] = FINF; }
        #pragma unroll
        for (int j = 0; j < 4; j++) {
            int cb = wn0 + j * 8 + (lane & 3) * 2;
            int tc0 = tCol[buf][cb], tc1 = tCol[buf][cb + 1];
            float sc0 = sqCol[buf][cb], sc1 = sqCol[buf][cb + 1];
            #pragma unroll
            for (int i = 0; i < 2; i++)
                #pragma unroll
                for (int h = 0; h < 2; h++) {
                    float d0 = fmaxf(fmaf(-2.0f, acc[i][j][2 * h],     sqr[i][h] + sc0), 0.0f);
                    float d1 = fmaxf(fmaf(-2.0f, acc[i][j][2 * h + 1], sqr[i][h] + sc1), 0.0f);
                    if (trow[i][h] == tc0) { mp[i][h] = fmaxf(mp[i][h], d0);
                                             cmax[j][0] = fmaxf(cmax[j][0], d0); }
                    else                   { mn[i][h] = fminf(mn[i][h], d0);
                                             cmin[j][0] = fminf(cmin[j][0], d0); }
                    if (trow[i][h] == tc1) { mp[i][h] = fmaxf(mp[i][h], d1);
                                             cmax[j][1] = fmaxf(cmax[j][1], d1); }
                    else                   { mn[i][h] = fminf(mn[i][h], d1);
                                             cmin[j][1] = fminf(cmin[j][1], d1); }
                }
        }
        // Butterfly over the 8 row-lane-groups, then no-return global atomics.
        #pragma unroll
        for (int j = 0; j < 4; j++)
            #pragma unroll
            for (int e = 0; e < 2; e++) {
                #pragma unroll
                for (int o = 4; o <= 16; o <<= 1) {
                    cmax[j][e] = fmaxf(cmax[j][e], __shfl_xor_sync(0xffffffffu, cmax[j][e], o));
                    cmin[j][e] = fminf(cmin[j][e], __shfl_xor_sync(0xffffffffu, cmin[j][e], o));
                }
            }
        if (lane < 4) {
            int colbase = s_J[buf] * BN + wn0;
            #pragma unroll
            for (int j = 0; j < 4; j++)
                #pragma unroll
                for (int e = 0; e < 2; e++) {
                    int gcol = colbase + j * 8 + lane * 2 + e;
                    atomicMax(&g_maxp[gcol], __float_as_int(cmax[j][e]));
                    atomicMin(&g_minn[gcol], __float_as_int(cmin[j][e]));
                }
        }
    }

    // Row stats: reduce over 4 lanes/row, then order-independent atomics
    // (4 N-quarter warps contribute per row).
    #pragma unroll
    for (int i = 0; i < 2; i++)
        #pragma unroll
        for (int h = 0; h < 2; h++) {
            #pragma unroll
            for (int o = 1; o <= 2; o <<= 1) {
                mp[i][h] = fmaxf(mp[i][h], __shfl_xor_sync(0xffffffffu, mp[i][h], o));
                mn[i][h] = fminf(mn[i][h], __shfl_xor_sync(0xffffffffu, mn[i][h], o));
            }
            if ((lane & 3) == 0) {
                int gr = row0 + wm0 + i * 16 + h * 8 + (lane >> 2);
                atomicMax(&g_maxp[gr], __float_as_int(mp[i][h]));
                atomicMin(&g_minn[gr], __float_as_int(mn[i][h]));
            }
        }
}

// ---------------------------------------------------------------------------
// Finalize: 16 rows/block, thread (r,c); X read straight from L2, cnt in smem.
__global__ void k_finalize(const float* __restrict__ X) {
    __shared__ float cnt[D * 16];   // transposed [k][c]
    __shared__ float terms[16];
    const int b = blockIdx.x, tid = threadIdx.x;
    const int row0 = b * 16;

    for (int i = tid; i < P * D; i += 256) {
        int k = i >> 4, c = i & 15;
        cnt[k * 16 + c] = g_cn[c * D + k];
    }
    __syncthreads();

    const int r = tid >> 4, c = tid & 15;
    const float4* xr = (const float4*)(X + (size_t)(row0 + r) * D);
    float d2 = 0.0f;
    #pragma unroll
    for (int k4 = 0; k4 < D / 4; k4++) {
        float4 v = __ldg(&xr[k4]);
        int k = k4 * 4;
        float f0 = v.x - cnt[(k + 0) * 16 + c];
        float f1 = v.y - cnt[(k + 1) * 16 + c];
        float f2 = v.z - cnt[(k + 2) * 16 + c];
        float f3 = v.w - cnt[(k + 3) * 16 + c];
        d2 = fmaf(f0, f0, d2); d2 = fmaf(f1, f1, d2);
        d2 = fmaf(f2, f2, d2); d2 = fmaf(f3, f3, d2);
    }
    float dc = fmaxf(sqrtf(d2), EPSF);
    #pragma unroll
    for (int o = 8; o; o >>= 1) dc = fminf(dc, __shfl_xor_sync(0xffffffffu, dc, o));

    if (c == 0) {
        int row = row0 + r;
        float mpv = __int_as_float(g_maxp[row]);
        float mnv = __int_as_float(g_minn[row]);
        float dap = sqrtf(fmaxf(mpv, EPSF));
        float dan = isinf(mnv) ? (dap + MARGINF) : sqrtf(fmaxf(mnv, EPSF));
        dan = fminf(dan, dc);
        terms[r] = fmaxf(dap - dan + MARGINF, 0.0f);
    }
    __syncthreads();
    if (tid == 0) {
        float s = 0.0f;
        #pragma unroll
        for (int i = 0; i < 16; i++) s += terms[i];
        g_partials[b] = s;
    }
}

__global__ void k_sum(float* __restrict__ out) {
    __shared__ float sh[512];
    int t = threadIdx.x;
    sh[t] = g_partials[t];
    __syncthreads();
    for (int s = 256; s; s >>= 1) {
        if (t < s) sh[t] += sh[t + s];
        __syncthreads();
    }
    if (t == 0) out[0] = sh[0] / (float)N;
}

// ---------------------------------------------------------------------------
extern "C" void kernel_launch(void* const* d_in, const int* in_sizes, int n_in,
                              void* d_out, int out_size) {
    const float* X = (const float*)d_in[0];
    const int*   T = (const int*)d_in[1];
    const float* C = (const float*)d_in[2];
    float* out = (float*)d_out;

    size_t smem = 196608;   // A hi/lo 64KB + B double buffer 128KB
    cudaFuncSetAttribute(k_main, cudaFuncAttributeMaxDynamicSharedMemorySize, (int)smem);

    k_split<<<N / 8, 256>>>(X);
    k_prep<<<1, P * 32>>>(C);
    k_main<<<dim3(NB, 2), 512, smem>>>(X, T);
    k_finalize<<<N / 16, 256>>>(X);
    k_sum<<<1, 512>>>(out);
}